// round 16
// baseline (speedup 1.0000x reference)
#include <cuda_runtime.h>
#include <cuda_bf16.h>
#include <cuda_fp16.h>
#include <mma.h>
using namespace nvcuda;

#define NN     50000
#define PADN   50048          // 64-row padded for wmma tiles
#define ER     1600000
#define ET     1650000        // edges + self loops
#define INCH   128
#define J1     96             // HEADS*HID
#define HEADS  3
#define HID    32
#define OC     32
#define NEG    0.2f

#define NW1    24             // h1 fp8x4 words per node (96 ch)
#define NW2    8              // h2 fp8x4 words per node (32 ch)
#define NO1    48             // o1 bf16x2 words per node (96 ch)

#define SCAN_CHUNK 1024
#define NCHUNK ((NN + SCAN_CHUNK - 1) / SCAN_CHUNK)   // 49

// ---------------- scratch (device globals; no allocation allowed) ----------------
__device__ int   g_fmt;                       // 0 = int64 edge buffer, 1 = int32
__device__ __align__(16) int                g_deg [NN];
__device__ __align__(16) int                g_off [NN + 1];
__device__ __align__(16) int                g_cur [NN];
__device__ __align__(16) unsigned long long g_stat[NCHUNK];  // decoupled-lookback status
__device__ __align__(16) unsigned short     g_csrc[ET];      // CSR src ids (fit in u16)
__device__ __align__(16) __nv_bfloat16      g_W1b [INCH * J1];
__device__ __align__(16) __nv_bfloat16      g_W2b [J1 * OC];
__device__ __align__(16) unsigned           g_h1b [NN * NW1]; // h1 fp8x4 (e4m3)
__device__ __align__(16) float              g_as1 [NN * 4];
__device__ __align__(16) float              g_ad1 [NN * 4];
__device__ __align__(16) unsigned           g_o1b [NN * NO1]; // o1 bf16x2
__device__ __align__(16) unsigned           g_h2b [NN * NW2]; // h2 fp8x4 (e4m3)
__device__ __align__(16) float              g_as2 [NN];
__device__ __align__(16) float              g_ad2 [NN];

// ---------------- helpers ----------------
__device__ __forceinline__ float bsum(float v) {
    v += __shfl_xor_sync(0xffffffffu, v, 16);
    v += __shfl_xor_sync(0xffffffffu, v, 8);
    v += __shfl_xor_sync(0xffffffffu, v, 4);
    v += __shfl_xor_sync(0xffffffffu, v, 2);
    v += __shfl_xor_sync(0xffffffffu, v, 1);
    return v;
}
__device__ __forceinline__ int clampi(int v) {
    return v < 0 ? 0 : (v >= NN ? NN - 1 : v);
}
__device__ __forceinline__ float lrelu_exp(float v) {
    v = v > 0.f ? v : NEG * v;
    return __expf(v);
}
__device__ __forceinline__ unsigned packbf(float a, float b) {
    __nv_bfloat162 t = __floats2bfloat162_rn(a, b);
    return *(unsigned*)&t;
}
__device__ __forceinline__ float2 unpackbf(unsigned u) {
    __nv_bfloat162 t = *(__nv_bfloat162*)&u;
    return __bfloat1622float2(t);
}
__device__ __forceinline__ unsigned pack4_fp8(float c0, float c1, float c2, float c3) {
    unsigned short lo, hi;
    asm("cvt.rn.satfinite.e4m3x2.f32 %0, %1, %2;" : "=h"(lo) : "f"(c1), "f"(c0));
    asm("cvt.rn.satfinite.e4m3x2.f32 %0, %1, %2;" : "=h"(hi) : "f"(c3), "f"(c2));
    return ((unsigned)hi << 16) | (unsigned)lo;
}
__device__ __forceinline__ float4 unpack4_fp8(unsigned u) {
    unsigned h0, h1;
    unsigned short lo = (unsigned short)(u & 0xffffu), hi = (unsigned short)(u >> 16);
    asm("cvt.rn.f16x2.e4m3x2 %0, %1;" : "=r"(h0) : "h"(lo));
    asm("cvt.rn.f16x2.e4m3x2 %0, %1;" : "=r"(h1) : "h"(hi));
    __half2 a = *(__half2*)&h0, b = *(__half2*)&h1;
    float2 fa = __half22float2(a), fb = __half22float2(b);
    return make_float4(fa.x, fa.y, fb.x, fb.y);
}

// ---------------- kernels ----------------
// init: zero deg + scan status; detect edge dtype (block 0); convert W1/W2; off[NN]=ET.
__global__ void k_init(const int* __restrict__ ei32,
                       const float* __restrict__ W1, const float* __restrict__ W2) {
    int i = blockIdx.x * blockDim.x + threadIdx.x;
    if (i < NN) g_deg[i] = 0;
    if (i < NCHUNK) g_stat[i] = 0ull;
    if (i == 0) g_off[NN] = ET;
    int w = i * 4;
    if (w < INCH * J1) {
        float4 v = *(const float4*)&W1[w];
        *(uint2*)&g_W1b[w] = make_uint2(packbf(v.x, v.y), packbf(v.z, v.w));
    }
    if (w < J1 * OC) {
        float4 v = *(const float4*)&W2[w];
        *(uint2*)&g_W2b[w] = make_uint2(packbf(v.x, v.y), packbf(v.z, v.w));
    }
    if (blockIdx.x == 0) {
        __shared__ int nz;
        if (threadIdx.x == 0) nz = 0;
        __syncthreads();
        for (int k = threadIdx.x; k < 2048; k += blockDim.x)
            if (ei32[2 * k * 391 + 1] != 0) atomicOr(&nz, 1);
        __syncthreads();
        if (threadIdx.x == 0) g_fmt = nz ? 1 : 0;
    }
}

// histogram of dst degrees; 4 edges per thread (dst half only).
__global__ void k_hist(const void* __restrict__ eiv) {
    int t = blockIdx.x * blockDim.x + threadIdx.x;
    if (t >= ER / 4) return;
    int d0, d1, d2, d3;
    if (g_fmt == 0) {
        longlong2 a = ((const longlong2*)eiv)[ER / 2 + 2 * t];
        longlong2 b = ((const longlong2*)eiv)[ER / 2 + 2 * t + 1];
        d0 = (int)a.x; d1 = (int)a.y; d2 = (int)b.x; d3 = (int)b.y;
    } else {
        int4 v = ((const int4*)eiv)[ER / 4 + t];
        d0 = v.x; d1 = v.y; d2 = v.z; d3 = v.w;
    }
    atomicAdd(&g_deg[clampi(d0)], 1);
    atomicAdd(&g_deg[clampi(d1)], 1);
    atomicAdd(&g_deg[clampi(d2)], 1);
    atomicAdd(&g_deg[clampi(d3)], 1);
}

// Single-pass exclusive scan of (deg+1) with decoupled lookback.
// 49 blocks (one resident wave). Also fills g_cur and places self-loops.
__global__ void k_scan() {
    __shared__ int warpsums[32];
    __shared__ int sh_T, sh_run;
    int tid = threadIdx.x, lane = tid & 31, wid = tid >> 5;
    int bid = blockIdx.x;
    int i = bid * SCAN_CHUNK + tid;
    int v = (i < NN) ? (g_deg[i] + 1) : 0;    // +1: self loop
    int x = v;
    #pragma unroll
    for (int o = 1; o < 32; o <<= 1) {
        int y = __shfl_up_sync(0xffffffffu, x, o);
        if (lane >= o) x += y;
    }
    if (lane == 31) warpsums[wid] = x;
    __syncthreads();
    if (wid == 0) {
        int sv = warpsums[lane];
        #pragma unroll
        for (int o = 1; o < 32; o <<= 1) {
            int y = __shfl_up_sync(0xffffffffu, sv, o);
            if (lane >= o) sv += y;
        }
        warpsums[lane] = sv;
    }
    __syncthreads();
    int incl = x + (wid > 0 ? warpsums[wid - 1] : 0);
    if (tid == SCAN_CHUNK - 1) sh_T = incl;
    __syncthreads();
    int T = sh_T;
    if (tid == 0) {
        unsigned long long st = ((unsigned long long)T << 2) | (bid == 0 ? 2ull : 1ull);
        __threadfence();
        atomicExch(&g_stat[bid], st);
        if (bid == 0) sh_run = 0;
    }
    if (bid > 0 && tid < 32) {
        int running = 0;
        int j = bid - 1;
        while (true) {
            int idx = j - (int)tid;
            unsigned long long st;
            do {
                st = (idx >= 0) ? atomicAdd(&g_stat[idx], 0ull) : 2ull;
            } while (__any_sync(0xffffffffu, (st & 3ull) == 0ull));
            unsigned pm = __ballot_sync(0xffffffffu, (st & 3ull) == 2ull);
            int firstP = __ffs(pm) - 1;
            int contrib = ((int)tid <= firstP || firstP < 0) ? (int)(st >> 2) : 0;
            #pragma unroll
            for (int o = 16; o; o >>= 1) contrib += __shfl_xor_sync(0xffffffffu, contrib, o);
            running += contrib;
            if (firstP >= 0) break;
            j -= 32;
        }
        if (tid == 0) {
            sh_run = running;
            unsigned long long st2 = (((unsigned long long)(running + T)) << 2) | 2ull;
            __threadfence();
            atomicExch(&g_stat[bid], st2);
        }
    }
    __syncthreads();
    int off = sh_run + incl - v;
    if (i < NN) {
        g_off[i] = off;
        g_cur[i] = off;                           // real edges fill off .. off+deg-1
        g_csrc[off + v - 1] = (unsigned short)i;  // self loop at the last slot
    }
}

// scatter real edges only; 4 edges per thread.
__global__ void k_scatter(const void* __restrict__ eiv) {
    int t = blockIdx.x * blockDim.x + threadIdx.x;
    if (t >= ER / 4) return;
    int s0, s1, s2, s3, d0, d1, d2, d3;
    if (g_fmt == 0) {
        longlong2 sa = ((const longlong2*)eiv)[2 * t];
        longlong2 sb = ((const longlong2*)eiv)[2 * t + 1];
        longlong2 da = ((const longlong2*)eiv)[ER / 2 + 2 * t];
        longlong2 db = ((const longlong2*)eiv)[ER / 2 + 2 * t + 1];
        s0 = (int)sa.x; s1 = (int)sa.y; s2 = (int)sb.x; s3 = (int)sb.y;
        d0 = (int)da.x; d1 = (int)da.y; d2 = (int)db.x; d3 = (int)db.y;
    } else {
        int4 sp = ((const int4*)eiv)[t];
        int4 dp = ((const int4*)eiv)[ER / 4 + t];
        s0 = sp.x; s1 = sp.y; s2 = sp.z; s3 = sp.w;
        d0 = dp.x; d1 = dp.y; d2 = dp.z; d3 = dp.w;
    }
    s0 = clampi(s0); s1 = clampi(s1); s2 = clampi(s2); s3 = clampi(s3);
    d0 = clampi(d0); d1 = clampi(d1); d2 = clampi(d2); d3 = clampi(d3);
    int p0 = atomicAdd(&g_cur[d0], 1);
    int p1 = atomicAdd(&g_cur[d1], 1);
    int p2 = atomicAdd(&g_cur[d2], 1);
    int p3 = atomicAdd(&g_cur[d3], 1);
    g_csrc[p0] = (unsigned short)s0;
    g_csrc[p1] = (unsigned short)s1;
    g_csrc[p2] = (unsigned short)s2;
    g_csrc[p3] = (unsigned short)s3;
}

// h1 = x @ W1 via wmma bf16; x converted fp32->bf16 in-kernel (smem stage).
__global__ void k_gemm1(const float* __restrict__ x,
                        const float* __restrict__ aS, const float* __restrict__ aD) {
    __shared__ __nv_bfloat16 Ash[64][136];
    __shared__ float Csh[64][96];
    int tid = threadIdx.x;
    int wid = tid >> 5, tx = tid & 31;
    int base = blockIdx.x * 64;

    #pragma unroll
    for (int i = 0; i < 8; i++) {
        int idx4 = tid + 256 * i;
        int row = idx4 >> 5, c4 = (idx4 & 31) * 4;
        int gr = base + row;
        float4 v = (gr < NN) ? *(const float4*)&x[gr * INCH + c4]
                             : make_float4(0.f, 0.f, 0.f, 0.f);
        *(uint2*)&Ash[row][c4] = make_uint2(packbf(v.x, v.y), packbf(v.z, v.w));
    }
    __syncthreads();

    int mt  = wid >> 1;
    int nt0 = (wid & 1) * 3;
    wmma::fragment<wmma::matrix_a, 16, 16, 16, __nv_bfloat16, wmma::row_major> fa;
    wmma::fragment<wmma::matrix_b, 16, 16, 16, __nv_bfloat16, wmma::row_major> fb;
    wmma::fragment<wmma::accumulator, 16, 16, 16, float> fc[3];
    #pragma unroll
    for (int t = 0; t < 3; t++) wmma::fill_fragment(fc[t], 0.f);
    #pragma unroll
    for (int k0 = 0; k0 < INCH; k0 += 16) {
        wmma::load_matrix_sync(fa, &Ash[mt * 16][k0], 136);
        #pragma unroll
        for (int t = 0; t < 3; t++) {
            wmma::load_matrix_sync(fb, g_W1b + k0 * J1 + (nt0 + t) * 16, J1);
            wmma::mma_sync(fc[t], fa, fb, fc[t]);
        }
    }
    #pragma unroll
    for (int t = 0; t < 3; t++)
        wmma::store_matrix_sync(&Csh[mt * 16][(nt0 + t) * 16], fc[t], J1, wmma::mem_row_major);
    __syncthreads();

    float aSv[3], aDv[3];
    #pragma unroll
    for (int c = 0; c < 3; c++) { aSv[c] = aS[c * 32 + tx]; aDv[c] = aD[c * 32 + tx]; }
    #pragma unroll
    for (int i = 0; i < 8; i++) {
        int lrow = wid * 8 + i;
        int row = base + lrow;
        if (row >= NN) continue;            // warp-uniform
        #pragma unroll
        for (int c = 0; c < 3; c++) {
            float v0 = Csh[lrow][c * 32 + tx];
            float v1 = __shfl_down_sync(0xffffffffu, v0, 1);
            float v2 = __shfl_down_sync(0xffffffffu, v0, 2);
            float v3 = __shfl_down_sync(0xffffffffu, v0, 3);
            if (!(tx & 3))
                g_h1b[row * NW1 + c * 8 + (tx >> 2)] = pack4_fp8(v0, v1, v2, v3);
            float vs = bsum(v0 * aSv[c]);
            float vd = bsum(v0 * aDv[c]);
            if (tx == 0) { g_as1[row * 4 + c] = vs; g_ad1[row * 4 + c] = vd; }
        }
    }
}

// Fused layer-1 softmax + aggregation. Warp per dst node.
__global__ void k_fagg1() {
    int d = (int)((blockIdx.x * blockDim.x + threadIdx.x) >> 5);
    int lane = threadIdx.x & 31;
    if (d >= NN) return;
    int sub = lane >> 3, l8 = lane & 7;
    int beg = g_off[d], end = g_off[d + 1];
    float4 adv = *(const float4*)&g_ad1[d * 4];
    float4 a0 = {0.f,0.f,0.f,0.f}, a1 = {0.f,0.f,0.f,0.f}, a2 = {0.f,0.f,0.f,0.f};
    float sp0 = 0.f, sp1 = 0.f, sp2 = 0.f;
    for (int j = beg; j < end; j += 32) {
        int n = end - j; if (n > 32) n = 32;
        int s = 0; float p0 = 0.f, p1 = 0.f, p2 = 0.f;
        if (lane < n) {
            s = (int)g_csrc[j + lane];
            float4 a = *(const float4*)&g_as1[s * 4];
            p0 = lrelu_exp(a.x + adv.x);
            p1 = lrelu_exp(a.y + adv.y);
            p2 = lrelu_exp(a.z + adv.z);
            sp0 += p0; sp1 += p1; sp2 += p2;
        }
        for (int i = 0; i < n; i += 4) {
            int e2 = (i + sub) & 31;
            int   si = __shfl_sync(0xffffffffu, s,  e2);
            float q0 = __shfl_sync(0xffffffffu, p0, e2);
            float q1 = __shfl_sync(0xffffffffu, p1, e2);
            float q2 = __shfl_sync(0xffffffffu, p2, e2);
            if (i + sub < n) {
                const unsigned* hw = &g_h1b[si * NW1 + l8];
                float4 v0 = unpack4_fp8(hw[0]);
                float4 v1 = unpack4_fp8(hw[8]);
                float4 v2 = unpack4_fp8(hw[16]);
                a0.x += q0 * v0.x; a0.y += q0 * v0.y; a0.z += q0 * v0.z; a0.w += q0 * v0.w;
                a1.x += q1 * v1.x; a1.y += q1 * v1.y; a1.z += q1 * v1.z; a1.w += q1 * v1.w;
                a2.x += q2 * v2.x; a2.y += q2 * v2.y; a2.z += q2 * v2.z; a2.w += q2 * v2.w;
            }
        }
    }
    #pragma unroll
    for (int o = 8; o <= 16; o <<= 1) {
        a0.x += __shfl_xor_sync(0xffffffffu, a0.x, o); a0.y += __shfl_xor_sync(0xffffffffu, a0.y, o);
        a0.z += __shfl_xor_sync(0xffffffffu, a0.z, o); a0.w += __shfl_xor_sync(0xffffffffu, a0.w, o);
        a1.x += __shfl_xor_sync(0xffffffffu, a1.x, o); a1.y += __shfl_xor_sync(0xffffffffu, a1.y, o);
        a1.z += __shfl_xor_sync(0xffffffffu, a1.z, o); a1.w += __shfl_xor_sync(0xffffffffu, a1.w, o);
        a2.x += __shfl_xor_sync(0xffffffffu, a2.x, o); a2.y += __shfl_xor_sync(0xffffffffu, a2.y, o);
        a2.z += __shfl_xor_sync(0xffffffffu, a2.z, o); a2.w += __shfl_xor_sync(0xffffffffu, a2.w, o);
    }
    sp0 = bsum(sp0); sp1 = bsum(sp1); sp2 = bsum(sp2);
    float r0 = 1.f / (sp0 + 1e-16f);
    float r1 = 1.f / (sp1 + 1e-16f);
    float r2 = 1.f / (sp2 + 1e-16f);
    if (sub == 0) {
        unsigned* ob = &g_o1b[d * NO1];
        *(uint2*)&ob[2 * l8]      = make_uint2(packbf(a0.x * r0, a0.y * r0), packbf(a0.z * r0, a0.w * r0));
        *(uint2*)&ob[16 + 2 * l8] = make_uint2(packbf(a1.x * r1, a1.y * r1), packbf(a1.z * r1, a1.w * r1));
        *(uint2*)&ob[32 + 2 * l8] = make_uint2(packbf(a2.x * r2, a2.y * r2), packbf(a2.z * r2, a2.w * r2));
    }
}

// h2 = elu(o1 + b1) @ W2 via wmma bf16; o1 read as bf16, bias+ELU in fp32.
__global__ void k_gemm2(const float* __restrict__ b1,
                        const float* __restrict__ aS, const float* __restrict__ aD) {
    __shared__ __nv_bfloat16 Xb[64][104];
    __shared__ float Csh[64][32];
    int tid = threadIdx.x;
    int wid = tid >> 5, tx = tid & 31;
    int base = blockIdx.x * 64;

    #pragma unroll
    for (int i = 0; i < 3; i++) {
        int idx = tid + 256 * i;
        int row = idx / 12, g = idx % 12;
        int gr = base + row;
        uint4 w = (gr < NN) ? *(const uint4*)&g_o1b[gr * NO1 + 4 * g]
                            : make_uint4(0u, 0u, 0u, 0u);
        float2 f0 = unpackbf(w.x), f1 = unpackbf(w.y), f2 = unpackbf(w.z), f3 = unpackbf(w.w);
        float4 ba = *(const float4*)&b1[8 * g];
        float4 bb = *(const float4*)&b1[8 * g + 4];
        float e0 = f0.x + ba.x, e1 = f0.y + ba.y, e2 = f1.x + ba.z, e3 = f1.y + ba.w;
        float e4 = f2.x + bb.x, e5 = f2.y + bb.y, e6 = f3.x + bb.z, e7 = f3.y + bb.w;
        e0 = e0 > 0.f ? e0 : (__expf(e0) - 1.f);
        e1 = e1 > 0.f ? e1 : (__expf(e1) - 1.f);
        e2 = e2 > 0.f ? e2 : (__expf(e2) - 1.f);
        e3 = e3 > 0.f ? e3 : (__expf(e3) - 1.f);
        e4 = e4 > 0.f ? e4 : (__expf(e4) - 1.f);
        e5 = e5 > 0.f ? e5 : (__expf(e5) - 1.f);
        e6 = e6 > 0.f ? e6 : (__expf(e6) - 1.f);
        e7 = e7 > 0.f ? e7 : (__expf(e7) - 1.f);
        uint4 o;
        o.x = packbf(e0, e1); o.y = packbf(e2, e3);
        o.z = packbf(e4, e5); o.w = packbf(e6, e7);
        *(uint4*)&Xb[row][8 * g] = o;
    }
    __syncthreads();

    int mt = wid >> 1, nt = wid & 1;
    wmma::fragment<wmma::matrix_a, 16, 16, 16, __nv_bfloat16, wmma::row_major> fa;
    wmma::fragment<wmma::matrix_b, 16, 16, 16, __nv_bfloat16, wmma::row_major> fb;
    wmma::fragment<wmma::accumulator, 16, 16, 16, float> fc;
    wmma::fill_fragment(fc, 0.f);
    #pragma unroll
    for (int k0 = 0; k0 < J1; k0 += 16) {
        wmma::load_matrix_sync(fa, &Xb[mt * 16][k0], 104);
        wmma::load_matrix_sync(fb, g_W2b + k0 * OC + nt * 16, OC);
        wmma::mma_sync(fc, fa, fb, fc);
    }
    wmma::store_matrix_sync(&Csh[mt * 16][nt * 16], fc, OC, wmma::mem_row_major);
    __syncthreads();

    float aws = aS[tx], awd = aD[tx];
    #pragma unroll
    for (int i = 0; i < 8; i++) {
        int lrow = wid * 8 + i;
        int row = base + lrow;
        if (row >= NN) continue;            // warp-uniform
        float v0 = Csh[lrow][tx];
        float v1 = __shfl_down_sync(0xffffffffu, v0, 1);
        float v2 = __shfl_down_sync(0xffffffffu, v0, 2);
        float v3 = __shfl_down_sync(0xffffffffu, v0, 3);
        if (!(tx & 3)) g_h2b[row * NW2 + (tx >> 2)] = pack4_fp8(v0, v1, v2, v3);
        float vs = bsum(v0 * aws);
        float vd = bsum(v0 * awd);
        if (tx == 0) { g_as2[row] = vs; g_ad2[row] = vd; }
    }
}

// Fused layer-2: softmax + aggregation + bias + project + sigmoid.
__global__ void k_fagg2(const float* __restrict__ b2, const float* __restrict__ Wp,
                        const float* __restrict__ bp, float* __restrict__ out) {
    int d = (int)((blockIdx.x * blockDim.x + threadIdx.x) >> 5);
    int lane = threadIdx.x & 31;
    if (d >= NN) return;
    int sub = lane >> 3, l8 = lane & 7;
    int beg = g_off[d], end = g_off[d + 1];
    float adv = g_ad2[d];
    float4 acc = {0.f, 0.f, 0.f, 0.f};
    float sp = 0.f;
    for (int j = beg; j < end; j += 32) {
        int n = end - j; if (n > 32) n = 32;
        int s = 0; float p = 0.f;
        if (lane < n) {
            s = (int)g_csrc[j + lane];
            p = lrelu_exp(g_as2[s] + adv);
            sp += p;
        }
        for (int i = 0; i < n; i += 4) {
            int e2 = (i + sub) & 31;
            int   si = __shfl_sync(0xffffffffu, s, e2);
            float q  = __shfl_sync(0xffffffffu, p, e2);
            if (i + sub < n) {
                float4 v = unpack4_fp8(g_h2b[si * NW2 + l8]);
                acc.x += q * v.x; acc.y += q * v.y;
                acc.z += q * v.z; acc.w += q * v.w;
            }
        }
    }
    sp = bsum(sp);
    #pragma unroll
    for (int o = 8; o <= 16; o <<= 1) {
        acc.x += __shfl_xor_sync(0xffffffffu, acc.x, o);
        acc.y += __shfl_xor_sync(0xffffffffu, acc.y, o);
        acc.z += __shfl_xor_sync(0xffffffffu, acc.z, o);
        acc.w += __shfl_xor_sync(0xffffffffu, acc.w, o);
    }
    float r = 1.f / (sp + 1e-16f);
    float t = 0.f;
    if (sub == 0) {
        float o0 = acc.x * r + b2[4 * l8 + 0];
        float o1 = acc.y * r + b2[4 * l8 + 1];
        float o2 = acc.z * r + b2[4 * l8 + 2];
        float o3 = acc.w * r + b2[4 * l8 + 3];
        t = o0 * Wp[4 * l8 + 0] + o1 * Wp[4 * l8 + 1]
          + o2 * Wp[4 * l8 + 2] + o3 * Wp[4 * l8 + 3];
    }
    t = bsum(t);
    if (lane == 0) out[d] = 1.f / (1.f + __expf(-t - bp[0]));
}

// ---------------- launch ----------------
extern "C" void kernel_launch(void* const* d_in, const int* in_sizes, int n_in,
                              void* d_out, int out_size) {
    const float* x   = (const float*)d_in[0];
    const void*  ei  = d_in[1];
    const float* W1  = (const float*)d_in[2];
    const float* as1 = (const float*)d_in[3];
    const float* ad1 = (const float*)d_in[4];
    const float* b1  = (const float*)d_in[5];
    const float* W2  = (const float*)d_in[6];
    const float* as2 = (const float*)d_in[7];
    const float* ad2 = (const float*)d_in[8];
    const float* b2  = (const float*)d_in[9];
    const float* Wp  = (const float*)d_in[10];
    const float* bp  = (const float*)d_in[11];
    float* out = (float*)d_out;

    const int nodeWarpBlocks = (NN * 32 + 255) / 256;   // warp per node
    const int edge4Blocks    = (ER / 4 + 255) / 256;    // 4 edges per thread

    // fork-join: CSR build (stream 0) runs in parallel with gemm1 (per-thread stream).
    // kernel_launch is only invoked for the correctness run and the capture run,
    // so creating (and leaking) two small events per call is safe and deterministic.
    cudaEvent_t evFork, evJoin;
    cudaEventCreateWithFlags(&evFork, cudaEventDisableTiming);
    cudaEventCreateWithFlags(&evJoin, cudaEventDisableTiming);

    k_init<<<(NN + 255) / 256, 256>>>((const int*)ei, W1, W2);
    cudaEventRecord(evFork, (cudaStream_t)0);

    cudaStreamWaitEvent(cudaStreamPerThread, evFork, 0);
    k_gemm1<<<PADN / 64, 256, 0, cudaStreamPerThread>>>(x, as1, ad1);
    cudaEventRecord(evJoin, cudaStreamPerThread);

    k_hist<<<edge4Blocks, 256>>>(ei);
    k_scan<<<NCHUNK, SCAN_CHUNK>>>();
    k_scatter<<<edge4Blocks, 256>>>(ei);

    cudaStreamWaitEvent((cudaStream_t)0, evJoin, 0);
    k_fagg1<<<nodeWarpBlocks, 256>>>();
    k_gemm2<<<PADN / 64, 256>>>(b1, as2, ad2);
    k_fagg2<<<nodeWarpBlocks, 256>>>(b2, Wp, bp, out);
}

// round 17
// speedup vs baseline: 1.0028x; 1.0028x over previous
#include <cuda_runtime.h>
#include <cuda_bf16.h>
#include <cuda_fp16.h>
#include <mma.h>
using namespace nvcuda;

#define NN     50000
#define PADN   50048          // 64-row padded for wmma tiles
#define ER     1600000
#define ET     1650000        // edges + self loops
#define INCH   128
#define J1     96             // HEADS*HID
#define HEADS  3
#define HID    32
#define OC     32
#define NEG    0.2f

#define NW1    24             // h1 fp8x4 words per node (96 ch)
#define NW2    8              // h2 fp8x4 words per node (32 ch)
#define NO1    48             // o1 bf16x2 words per node (96 ch)

#define SCAN_CHUNK 1024
#define NCHUNK ((NN + SCAN_CHUNK - 1) / SCAN_CHUNK)   // 49

// ---------------- scratch (device globals; no allocation allowed) ----------------
__device__ int   g_fmt;                       // 0 = int64 edge buffer, 1 = int32
__device__ __align__(16) int                g_deg [NN];
__device__ __align__(16) int                g_off [NN + 1];
__device__ __align__(16) int                g_cur [NN];
__device__ __align__(16) unsigned long long g_stat[NCHUNK];  // decoupled-lookback status
__device__ __align__(16) unsigned short     g_csrc[ET];      // CSR src ids (fit in u16)
__device__ __align__(16) __nv_bfloat16      g_W1b [INCH * J1];
__device__ __align__(16) __nv_bfloat16      g_W2b [J1 * OC];
__device__ __align__(16) unsigned           g_h1b [NN * NW1]; // h1 fp8x4 (e4m3)
__device__ __align__(16) uint2              g_as1b[NN];       // src logits bf16x4 (3 heads)
__device__ __align__(16) float              g_ad1 [NN * 4];   // dst logits fp32 (read once/warp)
__device__ __align__(16) unsigned           g_o1b [NN * NO1]; // o1 bf16x2
__device__ __align__(16) unsigned           g_h2b [NN * NW2]; // h2 fp8x4 (e4m3)
__device__ __align__(16) float              g_as2 [NN];
__device__ __align__(16) float              g_ad2 [NN];

// ---------------- helpers ----------------
__device__ __forceinline__ float bsum(float v) {
    v += __shfl_xor_sync(0xffffffffu, v, 16);
    v += __shfl_xor_sync(0xffffffffu, v, 8);
    v += __shfl_xor_sync(0xffffffffu, v, 4);
    v += __shfl_xor_sync(0xffffffffu, v, 2);
    v += __shfl_xor_sync(0xffffffffu, v, 1);
    return v;
}
__device__ __forceinline__ int clampi(int v) {
    return v < 0 ? 0 : (v >= NN ? NN - 1 : v);
}
__device__ __forceinline__ float lrelu_exp(float v) {
    v = v > 0.f ? v : NEG * v;
    return __expf(v);
}
__device__ __forceinline__ unsigned packbf(float a, float b) {
    __nv_bfloat162 t = __floats2bfloat162_rn(a, b);
    return *(unsigned*)&t;
}
__device__ __forceinline__ float2 unpackbf(unsigned u) {
    __nv_bfloat162 t = *(__nv_bfloat162*)&u;
    return __bfloat1622float2(t);
}
__device__ __forceinline__ unsigned pack4_fp8(float c0, float c1, float c2, float c3) {
    unsigned short lo, hi;
    asm("cvt.rn.satfinite.e4m3x2.f32 %0, %1, %2;" : "=h"(lo) : "f"(c1), "f"(c0));
    asm("cvt.rn.satfinite.e4m3x2.f32 %0, %1, %2;" : "=h"(hi) : "f"(c3), "f"(c2));
    return ((unsigned)hi << 16) | (unsigned)lo;
}
__device__ __forceinline__ float4 unpack4_fp8(unsigned u) {
    unsigned h0, h1;
    unsigned short lo = (unsigned short)(u & 0xffffu), hi = (unsigned short)(u >> 16);
    asm("cvt.rn.f16x2.e4m3x2 %0, %1;" : "=r"(h0) : "h"(lo));
    asm("cvt.rn.f16x2.e4m3x2 %0, %1;" : "=r"(h1) : "h"(hi));
    __half2 a = *(__half2*)&h0, b = *(__half2*)&h1;
    float2 fa = __half22float2(a), fb = __half22float2(b);
    return make_float4(fa.x, fa.y, fb.x, fb.y);
}

// ---------------- kernels ----------------
// init: zero deg + scan status; detect edge dtype (block 0); convert W1/W2; off[NN]=ET.
__global__ void k_init(const int* __restrict__ ei32,
                       const float* __restrict__ W1, const float* __restrict__ W2) {
    int i = blockIdx.x * blockDim.x + threadIdx.x;
    if (i < NN) g_deg[i] = 0;
    if (i < NCHUNK) g_stat[i] = 0ull;
    if (i == 0) g_off[NN] = ET;
    int w = i * 4;
    if (w < INCH * J1) {
        float4 v = *(const float4*)&W1[w];
        *(uint2*)&g_W1b[w] = make_uint2(packbf(v.x, v.y), packbf(v.z, v.w));
    }
    if (w < J1 * OC) {
        float4 v = *(const float4*)&W2[w];
        *(uint2*)&g_W2b[w] = make_uint2(packbf(v.x, v.y), packbf(v.z, v.w));
    }
    if (blockIdx.x == 0) {
        __shared__ int nz;
        if (threadIdx.x == 0) nz = 0;
        __syncthreads();
        for (int k = threadIdx.x; k < 2048; k += blockDim.x)
            if (ei32[2 * k * 391 + 1] != 0) atomicOr(&nz, 1);
        __syncthreads();
        if (threadIdx.x == 0) g_fmt = nz ? 1 : 0;
    }
}

// histogram of dst degrees; 4 edges per thread (dst half only).
__global__ void k_hist(const void* __restrict__ eiv) {
    int t = blockIdx.x * blockDim.x + threadIdx.x;
    if (t >= ER / 4) return;
    int d0, d1, d2, d3;
    if (g_fmt == 0) {
        longlong2 a = ((const longlong2*)eiv)[ER / 2 + 2 * t];
        longlong2 b = ((const longlong2*)eiv)[ER / 2 + 2 * t + 1];
        d0 = (int)a.x; d1 = (int)a.y; d2 = (int)b.x; d3 = (int)b.y;
    } else {
        int4 v = ((const int4*)eiv)[ER / 4 + t];
        d0 = v.x; d1 = v.y; d2 = v.z; d3 = v.w;
    }
    atomicAdd(&g_deg[clampi(d0)], 1);
    atomicAdd(&g_deg[clampi(d1)], 1);
    atomicAdd(&g_deg[clampi(d2)], 1);
    atomicAdd(&g_deg[clampi(d3)], 1);
}

// Single-pass exclusive scan of (deg+1) with decoupled lookback.
__global__ void k_scan() {
    __shared__ int warpsums[32];
    __shared__ int sh_T, sh_run;
    int tid = threadIdx.x, lane = tid & 31, wid = tid >> 5;
    int bid = blockIdx.x;
    int i = bid * SCAN_CHUNK + tid;
    int v = (i < NN) ? (g_deg[i] + 1) : 0;    // +1: self loop
    int x = v;
    #pragma unroll
    for (int o = 1; o < 32; o <<= 1) {
        int y = __shfl_up_sync(0xffffffffu, x, o);
        if (lane >= o) x += y;
    }
    if (lane == 31) warpsums[wid] = x;
    __syncthreads();
    if (wid == 0) {
        int sv = warpsums[lane];
        #pragma unroll
        for (int o = 1; o < 32; o <<= 1) {
            int y = __shfl_up_sync(0xffffffffu, sv, o);
            if (lane >= o) sv += y;
        }
        warpsums[lane] = sv;
    }
    __syncthreads();
    int incl = x + (wid > 0 ? warpsums[wid - 1] : 0);
    if (tid == SCAN_CHUNK - 1) sh_T = incl;
    __syncthreads();
    int T = sh_T;
    if (tid == 0) {
        unsigned long long st = ((unsigned long long)T << 2) | (bid == 0 ? 2ull : 1ull);
        __threadfence();
        atomicExch(&g_stat[bid], st);
        if (bid == 0) sh_run = 0;
    }
    if (bid > 0 && tid < 32) {
        int running = 0;
        int j = bid - 1;
        while (true) {
            int idx = j - (int)tid;
            unsigned long long st;
            do {
                st = (idx >= 0) ? atomicAdd(&g_stat[idx], 0ull) : 2ull;
            } while (__any_sync(0xffffffffu, (st & 3ull) == 0ull));
            unsigned pm = __ballot_sync(0xffffffffu, (st & 3ull) == 2ull);
            int firstP = __ffs(pm) - 1;
            int contrib = ((int)tid <= firstP || firstP < 0) ? (int)(st >> 2) : 0;
            #pragma unroll
            for (int o = 16; o; o >>= 1) contrib += __shfl_xor_sync(0xffffffffu, contrib, o);
            running += contrib;
            if (firstP >= 0) break;
            j -= 32;
        }
        if (tid == 0) {
            sh_run = running;
            unsigned long long st2 = (((unsigned long long)(running + T)) << 2) | 2ull;
            __threadfence();
            atomicExch(&g_stat[bid], st2);
        }
    }
    __syncthreads();
    int off = sh_run + incl - v;
    if (i < NN) {
        g_off[i] = off;
        g_cur[i] = off;                           // real edges fill off .. off+deg-1
        g_csrc[off + v - 1] = (unsigned short)i;  // self loop at the last slot
    }
}

// scatter real edges only; 4 edges per thread.
__global__ void k_scatter(const void* __restrict__ eiv) {
    int t = blockIdx.x * blockDim.x + threadIdx.x;
    if (t >= ER / 4) return;
    int s0, s1, s2, s3, d0, d1, d2, d3;
    if (g_fmt == 0) {
        longlong2 sa = ((const longlong2*)eiv)[2 * t];
        longlong2 sb = ((const longlong2*)eiv)[2 * t + 1];
        longlong2 da = ((const longlong2*)eiv)[ER / 2 + 2 * t];
        longlong2 db = ((const longlong2*)eiv)[ER / 2 + 2 * t + 1];
        s0 = (int)sa.x; s1 = (int)sa.y; s2 = (int)sb.x; s3 = (int)sb.y;
        d0 = (int)da.x; d1 = (int)da.y; d2 = (int)db.x; d3 = (int)db.y;
    } else {
        int4 sp = ((const int4*)eiv)[t];
        int4 dp = ((const int4*)eiv)[ER / 4 + t];
        s0 = sp.x; s1 = sp.y; s2 = sp.z; s3 = sp.w;
        d0 = dp.x; d1 = dp.y; d2 = dp.z; d3 = dp.w;
    }
    s0 = clampi(s0); s1 = clampi(s1); s2 = clampi(s2); s3 = clampi(s3);
    d0 = clampi(d0); d1 = clampi(d1); d2 = clampi(d2); d3 = clampi(d3);
    int p0 = atomicAdd(&g_cur[d0], 1);
    int p1 = atomicAdd(&g_cur[d1], 1);
    int p2 = atomicAdd(&g_cur[d2], 1);
    int p3 = atomicAdd(&g_cur[d3], 1);
    g_csrc[p0] = (unsigned short)s0;
    g_csrc[p1] = (unsigned short)s1;
    g_csrc[p2] = (unsigned short)s2;
    g_csrc[p3] = (unsigned short)s3;
}

// h1 = x @ W1 via wmma bf16; x converted fp32->bf16 in-kernel (smem stage).
__global__ void k_gemm1(const float* __restrict__ x,
                        const float* __restrict__ aS, const float* __restrict__ aD) {
    __shared__ __nv_bfloat16 Ash[64][136];
    __shared__ float Csh[64][96];
    int tid = threadIdx.x;
    int wid = tid >> 5, tx = tid & 31;
    int base = blockIdx.x * 64;

    #pragma unroll
    for (int i = 0; i < 8; i++) {
        int idx4 = tid + 256 * i;
        int row = idx4 >> 5, c4 = (idx4 & 31) * 4;
        int gr = base + row;
        float4 v = (gr < NN) ? *(const float4*)&x[gr * INCH + c4]
                             : make_float4(0.f, 0.f, 0.f, 0.f);
        *(uint2*)&Ash[row][c4] = make_uint2(packbf(v.x, v.y), packbf(v.z, v.w));
    }
    __syncthreads();

    int mt  = wid >> 1;
    int nt0 = (wid & 1) * 3;
    wmma::fragment<wmma::matrix_a, 16, 16, 16, __nv_bfloat16, wmma::row_major> fa;
    wmma::fragment<wmma::matrix_b, 16, 16, 16, __nv_bfloat16, wmma::row_major> fb;
    wmma::fragment<wmma::accumulator, 16, 16, 16, float> fc[3];
    #pragma unroll
    for (int t = 0; t < 3; t++) wmma::fill_fragment(fc[t], 0.f);
    #pragma unroll
    for (int k0 = 0; k0 < INCH; k0 += 16) {
        wmma::load_matrix_sync(fa, &Ash[mt * 16][k0], 136);
        #pragma unroll
        for (int t = 0; t < 3; t++) {
            wmma::load_matrix_sync(fb, g_W1b + k0 * J1 + (nt0 + t) * 16, J1);
            wmma::mma_sync(fc[t], fa, fb, fc[t]);
        }
    }
    #pragma unroll
    for (int t = 0; t < 3; t++)
        wmma::store_matrix_sync(&Csh[mt * 16][(nt0 + t) * 16], fc[t], J1, wmma::mem_row_major);
    __syncthreads();

    float aSv[3], aDv[3];
    #pragma unroll
    for (int c = 0; c < 3; c++) { aSv[c] = aS[c * 32 + tx]; aDv[c] = aD[c * 32 + tx]; }
    #pragma unroll
    for (int i = 0; i < 8; i++) {
        int lrow = wid * 8 + i;
        int row = base + lrow;
        if (row >= NN) continue;            // warp-uniform
        float vsv[3], vdv[3];
        #pragma unroll
        for (int c = 0; c < 3; c++) {
            float v0 = Csh[lrow][c * 32 + tx];
            float v1 = __shfl_down_sync(0xffffffffu, v0, 1);
            float v2 = __shfl_down_sync(0xffffffffu, v0, 2);
            float v3 = __shfl_down_sync(0xffffffffu, v0, 3);
            if (!(tx & 3))
                g_h1b[row * NW1 + c * 8 + (tx >> 2)] = pack4_fp8(v0, v1, v2, v3);
            vsv[c] = bsum(v0 * aSv[c]);
            vdv[c] = bsum(v0 * aDv[c]);
        }
        if (tx == 0) {
            g_as1b[row] = make_uint2(packbf(vsv[0], vsv[1]), packbf(vsv[2], 0.f));
            float4 dv = { vdv[0], vdv[1], vdv[2], 0.f };
            *(float4*)&g_ad1[row * 4] = dv;
        }
    }
}

// Fused layer-1 softmax + aggregation. Warp per dst node.
__global__ void k_fagg1() {
    int d = (int)((blockIdx.x * blockDim.x + threadIdx.x) >> 5);
    int lane = threadIdx.x & 31;
    if (d >= NN) return;
    int sub = lane >> 3, l8 = lane & 7;
    int beg = g_off[d], end = g_off[d + 1];
    float4 adv = *(const float4*)&g_ad1[d * 4];
    float4 a0 = {0.f,0.f,0.f,0.f}, a1 = {0.f,0.f,0.f,0.f}, a2 = {0.f,0.f,0.f,0.f};
    float sp0 = 0.f, sp1 = 0.f, sp2 = 0.f;
    for (int j = beg; j < end; j += 32) {
        int n = end - j; if (n > 32) n = 32;
        int s = 0; float p0 = 0.f, p1 = 0.f, p2 = 0.f;
        if (lane < n) {
            s = (int)g_csrc[j + lane];
            uint2 ab = g_as1b[s];
            float2 a01 = unpackbf(ab.x);
            float2 a23 = unpackbf(ab.y);
            p0 = lrelu_exp(a01.x + adv.x);
            p1 = lrelu_exp(a01.y + adv.y);
            p2 = lrelu_exp(a23.x + adv.z);
            sp0 += p0; sp1 += p1; sp2 += p2;
        }
        for (int i = 0; i < n; i += 4) {
            int e2 = (i + sub) & 31;
            int   si = __shfl_sync(0xffffffffu, s,  e2);
            float q0 = __shfl_sync(0xffffffffu, p0, e2);
            float q1 = __shfl_sync(0xffffffffu, p1, e2);
            float q2 = __shfl_sync(0xffffffffu, p2, e2);
            if (i + sub < n) {
                const unsigned* hw = &g_h1b[si * NW1 + l8];
                float4 v0 = unpack4_fp8(hw[0]);
                float4 v1 = unpack4_fp8(hw[8]);
                float4 v2 = unpack4_fp8(hw[16]);
                a0.x += q0 * v0.x; a0.y += q0 * v0.y; a0.z += q0 * v0.z; a0.w += q0 * v0.w;
                a1.x += q1 * v1.x; a1.y += q1 * v1.y; a1.z += q1 * v1.z; a1.w += q1 * v1.w;
                a2.x += q2 * v2.x; a2.y += q2 * v2.y; a2.z += q2 * v2.z; a2.w += q2 * v2.w;
            }
        }
    }
    #pragma unroll
    for (int o = 8; o <= 16; o <<= 1) {
        a0.x += __shfl_xor_sync(0xffffffffu, a0.x, o); a0.y += __shfl_xor_sync(0xffffffffu, a0.y, o);
        a0.z += __shfl_xor_sync(0xffffffffu, a0.z, o); a0.w += __shfl_xor_sync(0xffffffffu, a0.w, o);
        a1.x += __shfl_xor_sync(0xffffffffu, a1.x, o); a1.y += __shfl_xor_sync(0xffffffffu, a1.y, o);
        a1.z += __shfl_xor_sync(0xffffffffu, a1.z, o); a1.w += __shfl_xor_sync(0xffffffffu, a1.w, o);
        a2.x += __shfl_xor_sync(0xffffffffu, a2.x, o); a2.y += __shfl_xor_sync(0xffffffffu, a2.y, o);
        a2.z += __shfl_xor_sync(0xffffffffu, a2.z, o); a2.w += __shfl_xor_sync(0xffffffffu, a2.w, o);
    }
    sp0 = bsum(sp0); sp1 = bsum(sp1); sp2 = bsum(sp2);
    float r0 = 1.f / (sp0 + 1e-16f);
    float r1 = 1.f / (sp1 + 1e-16f);
    float r2 = 1.f / (sp2 + 1e-16f);
    if (sub == 0) {
        unsigned* ob = &g_o1b[d * NO1];
        *(uint2*)&ob[2 * l8]      = make_uint2(packbf(a0.x * r0, a0.y * r0), packbf(a0.z * r0, a0.w * r0));
        *(uint2*)&ob[16 + 2 * l8] = make_uint2(packbf(a1.x * r1, a1.y * r1), packbf(a1.z * r1, a1.w * r1));
        *(uint2*)&ob[32 + 2 * l8] = make_uint2(packbf(a2.x * r2, a2.y * r2), packbf(a2.z * r2, a2.w * r2));
    }
}

// h2 = elu(o1 + b1) @ W2 via wmma bf16; o1 read as bf16, bias+ELU in fp32.
__global__ void k_gemm2(const float* __restrict__ b1,
                        const float* __restrict__ aS, const float* __restrict__ aD) {
    __shared__ __nv_bfloat16 Xb[64][104];
    __shared__ float Csh[64][32];
    int tid = threadIdx.x;
    int wid = tid >> 5, tx = tid & 31;
    int base = blockIdx.x * 64;

    #pragma unroll
    for (int i = 0; i < 3; i++) {
        int idx = tid + 256 * i;
        int row = idx / 12, g = idx % 12;
        int gr = base + row;
        uint4 w = (gr < NN) ? *(const uint4*)&g_o1b[gr * NO1 + 4 * g]
                            : make_uint4(0u, 0u, 0u, 0u);
        float2 f0 = unpackbf(w.x), f1 = unpackbf(w.y), f2 = unpackbf(w.z), f3 = unpackbf(w.w);
        float4 ba = *(const float4*)&b1[8 * g];
        float4 bb = *(const float4*)&b1[8 * g + 4];
        float e0 = f0.x + ba.x, e1 = f0.y + ba.y, e2 = f1.x + ba.z, e3 = f1.y + ba.w;
        float e4 = f2.x + bb.x, e5 = f2.y + bb.y, e6 = f3.x + bb.z, e7 = f3.y + bb.w;
        e0 = e0 > 0.f ? e0 : (__expf(e0) - 1.f);
        e1 = e1 > 0.f ? e1 : (__expf(e1) - 1.f);
        e2 = e2 > 0.f ? e2 : (__expf(e2) - 1.f);
        e3 = e3 > 0.f ? e3 : (__expf(e3) - 1.f);
        e4 = e4 > 0.f ? e4 : (__expf(e4) - 1.f);
        e5 = e5 > 0.f ? e5 : (__expf(e5) - 1.f);
        e6 = e6 > 0.f ? e6 : (__expf(e6) - 1.f);
        e7 = e7 > 0.f ? e7 : (__expf(e7) - 1.f);
        uint4 o;
        o.x = packbf(e0, e1); o.y = packbf(e2, e3);
        o.z = packbf(e4, e5); o.w = packbf(e6, e7);
        *(uint4*)&Xb[row][8 * g] = o;
    }
    __syncthreads();

    int mt = wid >> 1, nt = wid & 1;
    wmma::fragment<wmma::matrix_a, 16, 16, 16, __nv_bfloat16, wmma::row_major> fa;
    wmma::fragment<wmma::matrix_b, 16, 16, 16, __nv_bfloat16, wmma::row_major> fb;
    wmma::fragment<wmma::accumulator, 16, 16, 16, float> fc;
    wmma::fill_fragment(fc, 0.f);
    #pragma unroll
    for (int k0 = 0; k0 < J1; k0 += 16) {
        wmma::load_matrix_sync(fa, &Xb[mt * 16][k0], 104);
        wmma::load_matrix_sync(fb, g_W2b + k0 * OC + nt * 16, OC);
        wmma::mma_sync(fc, fa, fb, fc);
    }
    wmma::store_matrix_sync(&Csh[mt * 16][nt * 16], fc, OC, wmma::mem_row_major);
    __syncthreads();

    float aws = aS[tx], awd = aD[tx];
    #pragma unroll
    for (int i = 0; i < 8; i++) {
        int lrow = wid * 8 + i;
        int row = base + lrow;
        if (row >= NN) continue;            // warp-uniform
        float v0 = Csh[lrow][tx];
        float v1 = __shfl_down_sync(0xffffffffu, v0, 1);
        float v2 = __shfl_down_sync(0xffffffffu, v0, 2);
        float v3 = __shfl_down_sync(0xffffffffu, v0, 3);
        if (!(tx & 3)) g_h2b[row * NW2 + (tx >> 2)] = pack4_fp8(v0, v1, v2, v3);
        float vs = bsum(v0 * aws);
        float vd = bsum(v0 * awd);
        if (tx == 0) { g_as2[row] = vs; g_ad2[row] = vd; }
    }
}

// Fused layer-2: softmax + aggregation + bias + project + sigmoid.
__global__ void k_fagg2(const float* __restrict__ b2, const float* __restrict__ Wp,
                        const float* __restrict__ bp, float* __restrict__ out) {
    int d = (int)((blockIdx.x * blockDim.x + threadIdx.x) >> 5);
    int lane = threadIdx.x & 31;
    if (d >= NN) return;
    int sub = lane >> 3, l8 = lane & 7;
    int beg = g_off[d], end = g_off[d + 1];
    float adv = g_ad2[d];
    float4 acc = {0.f, 0.f, 0.f, 0.f};
    float sp = 0.f;
    for (int j = beg; j < end; j += 32) {
        int n = end - j; if (n > 32) n = 32;
        int s = 0; float p = 0.f;
        if (lane < n) {
            s = (int)g_csrc[j + lane];
            p = lrelu_exp(g_as2[s] + adv);
            sp += p;
        }
        for (int i = 0; i < n; i += 4) {
            int e2 = (i + sub) & 31;
            int   si = __shfl_sync(0xffffffffu, s, e2);
            float q  = __shfl_sync(0xffffffffu, p, e2);
            if (i + sub < n) {
                float4 v = unpack4_fp8(g_h2b[si * NW2 + l8]);
                acc.x += q * v.x; acc.y += q * v.y;
                acc.z += q * v.z; acc.w += q * v.w;
            }
        }
    }
    sp = bsum(sp);
    #pragma unroll
    for (int o = 8; o <= 16; o <<= 1) {
        acc.x += __shfl_xor_sync(0xffffffffu, acc.x, o);
        acc.y += __shfl_xor_sync(0xffffffffu, acc.y, o);
        acc.z += __shfl_xor_sync(0xffffffffu, acc.z, o);
        acc.w += __shfl_xor_sync(0xffffffffu, acc.w, o);
    }
    float r = 1.f / (sp + 1e-16f);
    float t = 0.f;
    if (sub == 0) {
        float o0 = acc.x * r + b2[4 * l8 + 0];
        float o1 = acc.y * r + b2[4 * l8 + 1];
        float o2 = acc.z * r + b2[4 * l8 + 2];
        float o3 = acc.w * r + b2[4 * l8 + 3];
        t = o0 * Wp[4 * l8 + 0] + o1 * Wp[4 * l8 + 1]
          + o2 * Wp[4 * l8 + 2] + o3 * Wp[4 * l8 + 3];
    }
    t = bsum(t);
    if (lane == 0) out[d] = 1.f / (1.f + __expf(-t - bp[0]));
}

// ---------------- launch ----------------
extern "C" void kernel_launch(void* const* d_in, const int* in_sizes, int n_in,
                              void* d_out, int out_size) {
    const float* x   = (const float*)d_in[0];
    const void*  ei  = d_in[1];
    const float* W1  = (const float*)d_in[2];
    const float* as1 = (const float*)d_in[3];
    const float* ad1 = (const float*)d_in[4];
    const float* b1  = (const float*)d_in[5];
    const float* W2  = (const float*)d_in[6];
    const float* as2 = (const float*)d_in[7];
    const float* ad2 = (const float*)d_in[8];
    const float* b2  = (const float*)d_in[9];
    const float* Wp  = (const float*)d_in[10];
    const float* bp  = (const float*)d_in[11];
    float* out = (float*)d_out;

    const int nodeWarpBlocks = (NN * 32 + 255) / 256;   // warp per node
    const int edge4Blocks    = (ER / 4 + 255) / 256;    // 4 edges per thread

    k_init<<<(NN + 255) / 256, 256>>>((const int*)ei, W1, W2);
    k_hist<<<edge4Blocks, 256>>>(ei);
    k_scan<<<NCHUNK, SCAN_CHUNK>>>();
    k_scatter<<<edge4Blocks, 256>>>(ei);
    k_gemm1<<<PADN / 64, 256>>>(x, as1, ad1);
    k_fagg1<<<nodeWarpBlocks, 256>>>();
    k_gemm2<<<PADN / 64, 256>>>(b1, as2, ad2);
    k_fagg2<<<nodeWarpBlocks, 256>>>(b2, Wp, bp, out);
}